// round 7
// baseline (speedup 1.0000x reference)
#include <cuda_runtime.h>
#include <cuda_bf16.h>
#include <math.h>
#include <stdint.h>

// Problem dims
#define BB   4
#define LL   1024
#define DD   512
#define CHI  32
#define SS   4
#define NT   (BB*LL)          // 4096 tokens
#define CSC  (CHI*SS*CHI)     // 4096
#define NPAIR (NT/2)          // 2048 token pairs

// ---------------- scratch (__device__ globals, no allocs) ----------------
__device__ float g_site[(size_t)NT * CSC];       // x @ W_site + b_site     (64 MB)
__device__ float g_gate[(size_t)NT * DD];        // x @ W_gate + b_gate
__device__ float g_Bmat[(size_t)NT * CHI * CHI]; // B_t stored [t][r*32+l]
__device__ float g_P[(size_t)NPAIR * CHI * CHI]; // P_k = B_2k @ B_2k+1, [k][r*32+l]
__device__ float g_D[(size_t)NPAIR * CHI];       // d_k = c_2k @ B_2k+1
__device__ float g_WB[512 * 1024];               // pre-reduced site weights (fp32)
__device__ float g_bB[1024];                     // pre-reduced site bias
__device__ float g_c[(size_t)NT * CHI];          // c_t[r] = u_t @ B_t
__device__ float g_left[(size_t)NT * CHI];       // recorded left vectors
__device__ float g_y[(size_t)NT * DD];           // pre-LN y
__device__ float g_Wco[128 * 512];               // W_bridge @ W_out (fp32)
__device__ float g_bco[512];                     // b_bridge @ W_out + b_out

// pre-converted bf16 split operands
__device__ __nv_bfloat16 g_xh[(size_t)NT * DD],   g_xl[(size_t)NT * DD];
__device__ __nv_bfloat16 g_WsT_h[(size_t)CSC * DD], g_WsT_l[(size_t)CSC * DD];   // [n][k]
__device__ __nv_bfloat16 g_WgT_h[DD * DD],        g_WgT_l[DD * DD];
__device__ __nv_bfloat16 g_WBT_h[1024 * DD],      g_WBT_l[1024 * DD];
__device__ __nv_bfloat16 g_WcoT_h[DD * 128],      g_WcoT_l[DD * 128];
__device__ __nv_bfloat16 g_mh[(size_t)NT * 128],  g_ml[(size_t)NT * 128];

// ---------------- helpers ----------------
__device__ __forceinline__ uint32_t smem_u32(const void* p) {
    uint32_t a;
    asm("{ .reg .u64 t; cvta.to.shared.u64 t, %1; cvt.u32.u64 %0, t; }" : "=r"(a) : "l"(p));
    return a;
}
__device__ __forceinline__ void bsplit(float v, __nv_bfloat16& h, __nv_bfloat16& l)
{
    h = __float2bfloat16(v);
    l = __float2bfloat16(v - __bfloat162float(h));
}
#define CPA16(dst, src)  asm volatile("cp.async.cg.shared.global [%0], [%1], 16;" :: "r"(dst), "l"(src))
#define CPA_COMMIT()     asm volatile("cp.async.commit_group;" ::: "memory")
#define CPA_WAIT0()      asm volatile("cp.async.wait_group 0;" ::: "memory")
#define CPA_WAIT1()      asm volatile("cp.async.wait_group 1;" ::: "memory")

#define MMA_BF16(d, a0, a1, a2, a3, b0, b1)                                   \
    asm volatile("mma.sync.aligned.m16n8k16.row.col.f32.bf16.bf16.f32 "       \
                 "{%0,%1,%2,%3}, {%4,%5,%6,%7}, {%8,%9}, {%0,%1,%2,%3};\n"    \
                 : "+f"(d[0]), "+f"(d[1]), "+f"(d[2]), "+f"(d[3])             \
                 : "r"(a0), "r"(a1), "r"(a2), "r"(a3), "r"(b0), "r"(b1))

// ---------------- x -> bf16 split ----------------
__global__ void xcvt_kernel(const float* __restrict__ x)
{
    int i = blockIdx.x * 256 + threadIdx.x;      // NT*DD = 2M
    __nv_bfloat16 h, l;
    bsplit(x[i], h, l);
    g_xh[i] = h; g_xl[i] = l;
}

// ---------------- transpose + split: src[K][N] fp32 -> dh/dl[N][K] bf16 ----
__global__ void tsplit_kernel(const float* __restrict__ src,
                              __nv_bfloat16* __restrict__ dh,
                              __nv_bfloat16* __restrict__ dl, int K, int N)
{
    __shared__ float t[32][33];
    int bn = blockIdx.x * 32, bk = blockIdx.y * 32;
    int tx = threadIdx.x, ty = threadIdx.y;
#pragma unroll
    for (int i = ty; i < 32; i += 8)
        t[i][tx] = src[(size_t)(bk + i) * N + bn + tx];
    __syncthreads();
#pragma unroll
    for (int i = ty; i < 32; i += 8) {
        __nv_bfloat16 h, l;
        bsplit(t[tx][i], h, l);                  // = src[bk+tx][bn+i]
        dh[(size_t)(bn + i) * K + bk + tx] = h;
        dl[(size_t)(bn + i) * K + bk + tx] = l;
    }
}

// ---------------- prep: fuse bridge+out weights (fp32) ----------------
__global__ void prep_kernel(const float* __restrict__ Wb, const float* __restrict__ bb,
                            const float* __restrict__ Wo, const float* __restrict__ bo)
{
    int idx = blockIdx.x * blockDim.x + threadIdx.x;   // 0..65535
    int pr = idx >> 9, j = idx & 511;
    float s = 0.f;
#pragma unroll
    for (int i = 0; i < 32; ++i)
        s = fmaf(Wb[pr * 32 + i], Wo[i * 512 + j], s);
    g_Wco[idx] = s;
    if (idx < 512) {
        float c = bo[idx];
#pragma unroll
        for (int i = 0; i < 32; ++i)
            c = fmaf(bb[i], Wo[i * 512 + idx], c);
        g_bco[idx] = c;
    }
}

// ---------------- reduce W_site over physical index -> W_B (fp32) ----------
__global__ __launch_bounds__(256) void wb_kernel(const float* __restrict__ Ws,
                                                 const float* __restrict__ bs)
{
    int idx = blockIdx.x * 256 + threadIdx.x;          // 0 .. 512*1024-1
    int d = idx >> 10, rem = idx & 1023;
    int l = rem >> 5, r = rem & 31;
    const float* p = Ws + (size_t)d * 4096 + l * 128 + r;   // coalesced in r
    g_WB[(size_t)d * 1024 + r * 32 + l] = p[0] + p[32] + p[64] + p[96];
    if (idx < 1024) {
        int ll = idx >> 5, rr = idx & 31;
        const float* q = bs + ll * 128 + rr;
        g_bB[rr * 32 + ll] = q[0] + q[32] + q[64] + q[96];
    }
}

// ============ bf16-split tensor GEMM: C = A[MxK] @ B[KxN] + bias ===========
#define HG_SMEM (2 * 40960)

__device__ __forceinline__ void hg_load(uint32_t sb,
    const __nv_bfloat16* __restrict__ Ah, const __nv_bfloat16* __restrict__ Al,
    const __nv_bfloat16* __restrict__ Bh, const __nv_bfloat16* __restrict__ Bl,
    int bm, int bn, int K, int k0, int tid)
{
#pragma unroll
    for (int q = 0; q < 2; ++q) {
        int id = tid + 256 * q;                  // 0..511
        int r = id >> 2, c = id & 3;
        uint32_t so = (uint32_t)(r * 80 + c * 16);
        size_t goA = (size_t)(bm + r) * K + k0 + c * 8;
        size_t goB = (size_t)(bn + r) * K + k0 + c * 8;
        CPA16(sb + so,          Ah + goA);
        CPA16(sb + 10240 + so,  Al + goA);
        CPA16(sb + 20480 + so,  Bh + goB);
        CPA16(sb + 30720 + so,  Bl + goB);
    }
}

__device__ __forceinline__ void hg_compute(const char* ss, float acc[4][4][4],
                                           int m0w, int n0w, int g, int tg)
{
    const char* sa_h = ss;
    const char* sa_l = ss + 10240;
    const char* sb_h = ss + 20480;
    const char* sb_l = ss + 30720;
#pragma unroll
    for (int kk = 0; kk < 2; ++kk) {
        int kb = kk * 32 + tg * 4;               // byte offset within row
        uint32_t ah[4][4], al[4][4];
#pragma unroll
        for (int mi = 0; mi < 4; ++mi) {
            int r0 = m0w + mi * 16 + g;
            ah[mi][0] = *(const uint32_t*)(sa_h + r0 * 80 + kb);
            ah[mi][1] = *(const uint32_t*)(sa_h + (r0 + 8) * 80 + kb);
            ah[mi][2] = *(const uint32_t*)(sa_h + r0 * 80 + kb + 16);
            ah[mi][3] = *(const uint32_t*)(sa_h + (r0 + 8) * 80 + kb + 16);
            al[mi][0] = *(const uint32_t*)(sa_l + r0 * 80 + kb);
            al[mi][1] = *(const uint32_t*)(sa_l + (r0 + 8) * 80 + kb);
            al[mi][2] = *(const uint32_t*)(sa_l + r0 * 80 + kb + 16);
            al[mi][3] = *(const uint32_t*)(sa_l + (r0 + 8) * 80 + kb + 16);
        }
#pragma unroll
        for (int ni = 0; ni < 4; ++ni) {
            int n0 = n0w + ni * 8 + g;
            uint32_t bh0 = *(const uint32_t*)(sb_h + n0 * 80 + kb);
            uint32_t bh1 = *(const uint32_t*)(sb_h + n0 * 80 + kb + 16);
            uint32_t bl0 = *(const uint32_t*)(sb_l + n0 * 80 + kb);
            uint32_t bl1 = *(const uint32_t*)(sb_l + n0 * 80 + kb + 16);
#pragma unroll
            for (int mi = 0; mi < 4; ++mi) {
                MMA_BF16(acc[mi][ni], ah[mi][0], ah[mi][1], ah[mi][2], ah[mi][3], bh0, bh1);
                MMA_BF16(acc[mi][ni], ah[mi][0], ah[mi][1], ah[mi][2], ah[mi][3], bl0, bl1);
                MMA_BF16(acc[mi][ni], al[mi][0], al[mi][1], al[mi][2], al[mi][3], bh0, bh1);
            }
        }
    }
}

__global__ __launch_bounds__(256, 1)
void hgemm2_kernel(const __nv_bfloat16* __restrict__ Ah, const __nv_bfloat16* __restrict__ Al,
                   const __nv_bfloat16* __restrict__ Bh, const __nv_bfloat16* __restrict__ Bl,
                   const float* __restrict__ bias, float* __restrict__ C,
                   int M, int N, int K)
{
    extern __shared__ __align__(16) char smem[];
    const int tid = threadIdx.x;
    const int warp = tid >> 5, lane = tid & 31;
    const int g = lane >> 2, tg = lane & 3;
    const int m0w = (warp >> 2) * 64;            // 0 | 64
    const int n0w = (warp & 3) * 32;             // 0..96
    const int bm = blockIdx.y * 128, bn = blockIdx.x * 128;
    const uint32_t sb = smem_u32(smem);

    float acc[4][4][4];
#pragma unroll
    for (int i = 0; i < 4; ++i)
#pragma unroll
        for (int j = 0; j < 4; ++j)
#pragma unroll
            for (int e = 0; e < 4; ++e) acc[i][j][e] = 0.f;

    const int nk = K >> 5;
    hg_load(sb, Ah, Al, Bh, Bl, bm, bn, K, 0, tid);
    CPA_COMMIT();
    for (int i = 0; i < nk; ++i) {
        if (i + 1 < nk) {
            hg_load(sb + ((i + 1) & 1) * 40960, Ah, Al, Bh, Bl, bm, bn, K, (i + 1) * 32, tid);
            CPA_COMMIT();
            CPA_WAIT1();
        } else {
            CPA_WAIT0();
        }
        __syncthreads();
        hg_compute(smem + (i & 1) * 40960, acc, m0w, n0w, g, tg);
        __syncthreads();
    }

#pragma unroll
    for (int mi = 0; mi < 4; ++mi) {
        int row = bm + m0w + mi * 16 + g;
#pragma unroll
        for (int ni = 0; ni < 4; ++ni) {
            int col = bn + n0w + ni * 8 + 2 * tg;
            float b0 = bias[col], b1 = bias[col + 1];
            *(float2*)&C[(size_t)row * N + col] =
                make_float2(acc[mi][ni][0] + b0, acc[mi][ni][1] + b1);
            *(float2*)&C[(size_t)(row + 8) * N + col] =
                make_float2(acc[mi][ni][2] + b0, acc[mi][ni][3] + b1);
        }
    }
}

// ---------------- c_t[r] = sum_l u_t[l] * B_t[l][r] (8 tokens/block) -------
__global__ __launch_bounds__(256) void c_kernel(const float* __restrict__ x)
{
    int t = blockIdx.x * 8 + (threadIdx.x >> 5);
    int r = threadIdx.x & 31;
    float u = x[(size_t)t * DD + r];           // lane l holds u_l
    const float* brow = g_Bmat + (size_t)t * 1024 + r * 32;
    float4 b4[8];
#pragma unroll
    for (int q = 0; q < 8; ++q) b4[q] = __ldg((const float4*)(brow + 4 * q));
    float c = 0.f;
#pragma unroll
    for (int q = 0; q < 8; ++q) {
        c = fmaf(__shfl_sync(0xffffffffu, u, 4 * q + 0), b4[q].x, c);
        c = fmaf(__shfl_sync(0xffffffffu, u, 4 * q + 1), b4[q].y, c);
        c = fmaf(__shfl_sync(0xffffffffu, u, 4 * q + 2), b4[q].z, c);
        c = fmaf(__shfl_sync(0xffffffffu, u, 4 * q + 3), b4[q].w, c);
    }
    g_c[(size_t)t * 32 + r] = c;
}

// ------- pair precompute: P_k = B_2k @ B_2k+1,  d_k = c_2k @ B_2k+1 --------
// Layouts: g_Bmat[t][r*32+l] = B_t[l][r]; g_P[k][r*32+l] = P_k[l][r].
__global__ __launch_bounds__(256) void pairprep_kernel()
{
    __shared__ float sB0[1024], sB1[1024], sc[32];
    const int p = blockIdx.x;                    // global pair id
    const int tid = threadIdx.x;
    const float* b0 = g_Bmat + (size_t)(2 * p) * 1024;
    const float* b1 = g_Bmat + (size_t)(2 * p + 1) * 1024;
#pragma unroll
    for (int i = tid; i < 1024; i += 256) { sB0[i] = b0[i]; sB1[i] = b1[i]; }
    if (tid < 32) sc[tid] = g_c[(size_t)(2 * p) * 32 + tid];
    __syncthreads();
#pragma unroll
    for (int q = 0; q < 4; ++q) {
        int e = q * 256 + tid;                   // e = r*32 + l
        int r = e >> 5, l = e & 31;
        float acc = 0.f;
#pragma unroll
        for (int m = 0; m < 32; ++m)
            acc = fmaf(sB0[m * 32 + l], sB1[r * 32 + m], acc);  // B0[l][m]*B1[m][r]
        g_P[(size_t)p * 1024 + e] = acc;
    }
    if (tid < 32) {
        float acc = 0.f;
#pragma unroll
        for (int m = 0; m < 32; ++m)
            acc = fmaf(sc[m], sB1[tid * 32 + m], acc);          // c[m]*B1[m][r]
        g_D[(size_t)p * 32 + tid] = acc;
    }
}

// ---------------- fused double-step sequential scan ------------------------
// Pair (2k, 2k+1):  a0 = rsqrt(||v||^2);  left_2k = a0 v + u0
//   vt = a0 (v@B_2k) + c0;  a1 = rsqrt(||vt||^2);  left_2k+1 = a1 vt + u1
//   v' = a1 (a0 (v@P_k) + d_k) + c1       [P_k = B_2k B_2k+1, d_k = c0 B_2k+1]
struct PairBuf {
    float4 B[8]; float4 P[8];
    float c0, c1, u0, u1, d;
};

__device__ __forceinline__ void pair_pref(PairBuf& pb, int k,
    const float* Bbase, const float* Pbase, const float* cbase,
    const float* ubase, const float* dbase)
{
    if (k > NPAIR / BB - 1) k = NPAIR / BB - 1;
    const float* bp = Bbase + (size_t)(2 * k) * 1024;
    const float* pp = Pbase + (size_t)k * 1024;
#pragma unroll
    for (int q = 0; q < 8; ++q) {
        pb.B[q] = __ldg((const float4*)(bp + 4 * q));
        pb.P[q] = __ldg((const float4*)(pp + 4 * q));
    }
    pb.c0 = __ldg(cbase + (size_t)(2 * k) * 32);
    pb.c1 = __ldg(cbase + (size_t)(2 * k + 1) * 32);
    pb.u0 = __ldg(ubase + (size_t)(2 * k) * DD);
    pb.u1 = __ldg(ubase + (size_t)(2 * k + 1) * DD);
    pb.d  = __ldg(dbase + (size_t)k * 32);
}

__device__ __forceinline__ float pair_step(float v, const PairBuf& pb, float* lp)
{
    // s0 = ||v||^2 via butterfly (overlaps with the w-chains below)
    float s0 = v * v;
#pragma unroll
    for (int m = 16; m > 0; m >>= 1) s0 += __shfl_xor_sync(0xffffffffu, s0, m);

    // one broadcast of v serves both matvecs
    float w1a = 0.f, w1b = 0.f, w1c = 0.f, w1d = 0.f;
    float w2a = 0.f, w2b = 0.f, w2c = 0.f, w2d = 0.f;
#pragma unroll
    for (int q = 0; q < 8; q += 4) {
        float va, vb, vc, vd;
        va = __shfl_sync(0xffffffffu, v, 4*q + 0);
        vb = __shfl_sync(0xffffffffu, v, 4*q + 1);
        vc = __shfl_sync(0xffffffffu, v, 4*q + 2);
        vd = __shfl_sync(0xffffffffu, v, 4*q + 3);
        w1a = fmaf(va, pb.B[q].x, w1a); w2a = fmaf(va, pb.P[q].x, w2a);
        w1a = fmaf(vb, pb.B[q].y, w1a); w2a = fmaf(vb, pb.P[q].y, w2a);
        w1a = fmaf(vc, pb.B[q].z, w1a); w2a = fmaf(vc, pb.P[q].z, w2a);
        w1a = fmaf(vd, pb.B[q].w, w1a); w2a = fmaf(vd, pb.P[q].w, w2a);
        va = __shfl_sync(0xffffffffu, v, 4*q + 4);
        vb = __shfl_sync(0xffffffffu, v, 4*q + 5);
        vc = __shfl_sync(0xffffffffu, v, 4*q + 6);
        vd = __shfl_sync(0xffffffffu, v, 4*q + 7);
        w1b = fmaf(va, pb.B[q+1].x, w1b); w2b = fmaf(va, pb.P[q+1].x, w2b);
        w1b = fmaf(vb, pb.B[q+1].y, w1b); w2b = fmaf(vb, pb.P[q+1].y, w2b);
        w1b = fmaf(vc, pb.B[q+1].z, w1b); w2b = fmaf(vc, pb.P[q+1].z, w2b);
        w1b = fmaf(vd, pb.B[q+1].w, w1b); w2b = fmaf(vd, pb.P[q+1].w, w2b);
        va = __shfl_sync(0xffffffffu, v, 4*q + 8);
        vb = __shfl_sync(0xffffffffu, v, 4*q + 9);
        vc = __shfl_sync(0xffffffffu, v, 4*q + 10);
        vd = __shfl_sync(0xffffffffu, v, 4*q + 11);
        w1c = fmaf(va, pb.B[q+2].x, w1c); w2c = fmaf(va, pb.P[q+2].x, w2c);
        w1c = fmaf(vb, pb.B[q+2].y, w1c); w2c = fmaf(vb, pb.P[q+2].y, w2c);
        w1c = fmaf(vc, pb.B[q+2].z, w1c); w2c = fmaf(vc, pb.P[q+2].z, w2c);
        w1c = fmaf(vd, pb.B[q+2].w, w1c); w2c = fmaf(vd, pb.P[q+2].w, w2c);
        va = __shfl_sync(0xffffffffu, v, 4*q + 12);
        vb = __shfl_sync(0xffffffffu, v, 4*q + 13);
        vc = __shfl_sync(0xffffffffu, v, 4*q + 14);
        vd = __shfl_sync(0xffffffffu, v, 4*q + 15);
        w1d = fmaf(va, pb.B[q+3].x, w1d); w2d = fmaf(va, pb.P[q+3].x, w2d);
        w1d = fmaf(vb, pb.B[q+3].y, w1d); w2d = fmaf(vb, pb.P[q+3].y, w2d);
        w1d = fmaf(vc, pb.B[q+3].z, w1d); w2d = fmaf(vc, pb.P[q+3].z, w2d);
        w1d = fmaf(vd, pb.B[q+3].w, w1d); w2d = fmaf(vd, pb.P[q+3].w, w2d);
    }
    float w1 = (w1a + w1b) + (w1c + w1d);
    float w2 = (w2a + w2b) + (w2c + w2d);

    float a0 = rsqrtf(s0 + 1e-24f);              // s0==0 -> a0*v == 0 == h0
    lp[0] = fmaf(a0, v, pb.u0);                  // left_2k
    float vt = fmaf(a0, w1, pb.c0);              // v_2k

    float s1 = vt * vt;
#pragma unroll
    for (int m = 16; m > 0; m >>= 1) s1 += __shfl_xor_sync(0xffffffffu, s1, m);
    float a1 = rsqrtf(s1 + 1e-24f);
    lp[32] = fmaf(a1, vt, pb.u1);                // left_2k+1
    return fmaf(a1, fmaf(a0, w2, pb.d), pb.c1);  // v_2k+1
}

__global__ void scan_kernel(const float* __restrict__ x)
{
    const int b = blockIdx.x;
    const int r = threadIdx.x;                   // 0..31
    const size_t tg0 = (size_t)b * LL;
    const size_t pg0 = (size_t)b * (LL / 2);
    const float* Bbase = g_Bmat + tg0 * 1024 + r * 32;
    const float* Pbase = g_P + pg0 * 1024 + r * 32;
    const float* cbase = g_c + tg0 * 32 + r;
    const float* ubase = x + tg0 * DD + r;
    const float* dbase = g_D + pg0 * 32 + r;
    float* lp = g_left + tg0 * 32 + r;

    PairBuf A, Bf;
    pair_pref(A, 0, Bbase, Pbase, cbase, ubase, dbase);
    float v = 0.f;

#pragma unroll 1
    for (int k = 0; k < LL / 2; k += 2) {
        pair_pref(Bf, k + 1, Bbase, Pbase, cbase, ubase, dbase);
        v = pair_step(v, A, lp); lp += 64;
        pair_pref(A, k + 2, Bbase, Pbase, cbase, ubase, dbase);
        v = pair_step(v, Bf, lp); lp += 64;
    }
}

// ------- recover Mt per token; emit bf16 split for the final GEMM ----------
__global__ __launch_bounds__(128) void mrec_kernel()
{
    __shared__ float sleft[32];
    int t = blockIdx.x, tid = threadIdx.x;
    if (tid < 32) sleft[tid] = g_left[(size_t)t * 32 + tid];
    __syncthreads();
    const float* row = g_site + (size_t)t * CSC;
    float m = 0.f;
#pragma unroll
    for (int l = 0; l < 32; ++l)
        m = fmaf(sleft[l], __ldcs(row + l * 128 + tid), m);   // streaming, coalesced
    __nv_bfloat16 h, lo;
    bsplit(m, h, lo);
    g_mh[(size_t)t * 128 + tid] = h;
    g_ml[(size_t)t * 128 + tid] = lo;
}

// ---------------- LayerNorm + sigmoid-gated residual ----------------
__global__ __launch_bounds__(256) void post_kernel(const float* __restrict__ x,
                                                   const float* __restrict__ gamma,
                                                   const float* __restrict__ beta,
                                                   float* __restrict__ out)
{
    __shared__ float red[256];
    int t = blockIdx.x, tid = threadIdx.x;
    size_t base = (size_t)t * DD;
    int j0 = tid, j1 = tid + 256;
    float y0 = g_y[base + j0], y1 = g_y[base + j1];

    red[tid] = y0 + y1;
    __syncthreads();
    for (int st = 128; st > 0; st >>= 1) {
        if (tid < st) red[tid] += red[tid + st];
        __syncthreads();
    }
    float mu = red[0] * (1.f / 512.f);
    __syncthreads();

    float d0 = y0 - mu, d1 = y1 - mu;
    red[tid] = d0 * d0 + d1 * d1;
    __syncthreads();
    for (int st = 128; st > 0; st >>= 1) {
        if (tid < st) red[tid] += red[tid + st];
        __syncthreads();
    }
    float var = red[0] * (1.f / 512.f);
    float rstd = rsqrtf(var + 1e-6f);

    float yn0 = d0 * rstd * gamma[j0] + beta[j0];
    float yn1 = d1 * rstd * gamma[j1] + beta[j1];
    float gl0 = g_gate[base + j0], gl1 = g_gate[base + j1];
    float gt0 = 1.f / (1.f + expf(-gl0));
    float gt1 = 1.f / (1.f + expf(-gl1));
    float xv0 = x[base + j0], xv1 = x[base + j1];
    out[base + j0] = gt0 * yn0 + (1.f - gt0) * xv0;
    out[base + j1] = gt1 * yn1 + (1.f - gt1) * xv1;
}

// ---------------- launch ----------------
extern "C" void kernel_launch(void* const* d_in, const int* in_sizes, int n_in,
                              void* d_out, int out_size)
{
    (void)in_sizes; (void)n_in; (void)out_size;
    const float* x       = (const float*)d_in[0];
    const float* W_site  = (const float*)d_in[1];
    const float* b_site  = (const float*)d_in[2];
    const float* W_bridge= (const float*)d_in[3];
    const float* b_bridge= (const float*)d_in[4];
    const float* W_out   = (const float*)d_in[5];
    const float* b_out   = (const float*)d_in[6];
    const float* gamma   = (const float*)d_in[7];
    const float* beta    = (const float*)d_in[8];
    const float* W_gate  = (const float*)d_in[9];
    const float* b_gate  = (const float*)d_in[10];
    float* out = (float*)d_out;

    static float *p_site, *p_gate, *p_y, *p_WB, *p_bB, *p_Wco, *p_bco, *p_Bmat;
    static __nv_bfloat16 *p_xh, *p_xl, *p_WsTh, *p_WsTl, *p_WgTh, *p_WgTl,
                         *p_WBTh, *p_WBTl, *p_WcoTh, *p_WcoTl, *p_mh, *p_ml;
    static cudaStream_t s1;
    static cudaEvent_t ev0, evS, evG;
    static bool inited = false;
    if (!inited) {
        cudaGetSymbolAddress((void**)&p_site,  g_site);
        cudaGetSymbolAddress((void**)&p_gate,  g_gate);
        cudaGetSymbolAddress((void**)&p_y,     g_y);
        cudaGetSymbolAddress((void**)&p_WB,    g_WB);
        cudaGetSymbolAddress((void**)&p_bB,    g_bB);
        cudaGetSymbolAddress((void**)&p_Wco,   g_Wco);
        cudaGetSymbolAddress((void**)&p_bco,   g_bco);
        cudaGetSymbolAddress((void**)&p_Bmat,  g_Bmat);
        cudaGetSymbolAddress((void**)&p_xh,    g_xh);
        cudaGetSymbolAddress((void**)&p_xl,    g_xl);
        cudaGetSymbolAddress((void**)&p_WsTh,  g_WsT_h);
        cudaGetSymbolAddress((void**)&p_WsTl,  g_WsT_l);
        cudaGetSymbolAddress((void**)&p_WgTh,  g_WgT_h);
        cudaGetSymbolAddress((void**)&p_WgTl,  g_WgT_l);
        cudaGetSymbolAddress((void**)&p_WBTh,  g_WBT_h);
        cudaGetSymbolAddress((void**)&p_WBTl,  g_WBT_l);
        cudaGetSymbolAddress((void**)&p_WcoTh, g_WcoT_h);
        cudaGetSymbolAddress((void**)&p_WcoTl, g_WcoT_l);
        cudaGetSymbolAddress((void**)&p_mh,    g_mh);
        cudaGetSymbolAddress((void**)&p_ml,    g_ml);
        cudaStreamCreateWithFlags(&s1, cudaStreamNonBlocking);
        cudaEventCreateWithFlags(&ev0, cudaEventDisableTiming);
        cudaEventCreateWithFlags(&evS, cudaEventDisableTiming);
        cudaEventCreateWithFlags(&evG, cudaEventDisableTiming);
        cudaFuncSetAttribute(hgemm2_kernel, cudaFuncAttributeMaxDynamicSharedMemorySize, HG_SMEM);
        inited = true;
    }

    // shared prologue: x split (both branches need it)
    xcvt_kernel<<<(NT * DD) / 256, 256>>>(x);
    cudaEventRecord(ev0, 0);
    cudaStreamWaitEvent(s1, ev0, 0);

    // ---- side stream: prep + weight converts + site & gate GEMMs ----
    prep_kernel<<<256, 256, 0, s1>>>(W_bridge, b_bridge, W_out, b_out);
    tsplit_kernel<<<dim3(16, 4),  dim3(32, 8), 0, s1>>>(p_Wco,  p_WcoTh, p_WcoTl, 128, 512);
    tsplit_kernel<<<dim3(128,16), dim3(32, 8), 0, s1>>>(W_site, p_WsTh,  p_WsTl,  512, 4096);
    tsplit_kernel<<<dim3(16, 16), dim3(32, 8), 0, s1>>>(W_gate, p_WgTh,  p_WgTl,  512, 512);
    hgemm2_kernel<<<dim3(CSC/128, NT/128), 256, HG_SMEM, s1>>>(
        p_xh, p_xl, p_WsTh, p_WsTl, b_site, p_site, NT, CSC, DD);
    cudaEventRecord(evS, s1);
    hgemm2_kernel<<<dim3(DD/128, NT/128), 256, HG_SMEM, s1>>>(
        p_xh, p_xl, p_WgTh, p_WgTl, b_gate, p_gate, NT, DD, DD);
    cudaEventRecord(evG, s1);

    // ---- main stream: B-matrix path + pair products + scan ----
    wb_kernel<<<2048, 256>>>(W_site, b_site);
    tsplit_kernel<<<dim3(32, 16), dim3(32, 8)>>>(p_WB, p_WBTh, p_WBTl, 512, 1024);
    hgemm2_kernel<<<dim3(1024/128, NT/128), 256, HG_SMEM>>>(
        p_xh, p_xl, p_WBTh, p_WBTl, p_bB, p_Bmat, NT, 1024, DD);
    c_kernel<<<NT / 8, 256>>>(x);
    pairprep_kernel<<<NPAIR, 256>>>();
    scan_kernel<<<BB, 32>>>(x);

    // join: site needed for M recovery, then final GEMM
    cudaStreamWaitEvent(0, evS, 0);
    mrec_kernel<<<NT, 128>>>();
    hgemm2_kernel<<<dim3(DD/128, NT/128), 256, HG_SMEM>>>(
        p_mh, p_ml, p_WcoTh, p_WcoTl, p_bco, p_y, NT, DD, 128);

    // join: gate needed for the epilogue
    cudaStreamWaitEvent(0, evG, 0);
    post_kernel<<<NT, 256>>>(x, gamma, beta, out);
}

// round 8
// speedup vs baseline: 1.0600x; 1.0600x over previous
#include <cuda_runtime.h>
#include <cuda_bf16.h>
#include <math.h>
#include <stdint.h>

// Problem dims
#define BB   4
#define LL   1024
#define DD   512
#define CHI  32
#define SS   4
#define NT   (BB*LL)          // 4096 tokens
#define CSC  (CHI*SS*CHI)     // 4096

// ---------------- scratch (__device__ globals, no allocs) ----------------
__device__ float g_site[(size_t)NT * CSC];       // x @ W_site + b_site     (64 MB)
__device__ float g_gate[(size_t)NT * DD];        // x @ W_gate + b_gate
__device__ float g_Bmat[(size_t)NT * CHI * CHI]; // B_t stored [t][r*32+l]
__device__ float g_WB[512 * 1024];               // pre-reduced site weights (fp32)
__device__ float g_bB[1024];                     // pre-reduced site bias
__device__ float g_c[(size_t)NT * CHI];          // c_t[r] = u_t @ B_t
__device__ float g_left[(size_t)NT * CHI];       // recorded left vectors
__device__ float g_y[(size_t)NT * DD];           // pre-LN y
__device__ float g_Wco[128 * 512];               // W_bridge @ W_out (fp32)
__device__ float g_bco[512];                     // b_bridge @ W_out + b_out

// pre-converted bf16 split operands
__device__ __nv_bfloat16 g_xh[(size_t)NT * DD],   g_xl[(size_t)NT * DD];
__device__ __nv_bfloat16 g_WsT_h[(size_t)CSC * DD], g_WsT_l[(size_t)CSC * DD];   // [n][k]
__device__ __nv_bfloat16 g_WgT_h[DD * DD],        g_WgT_l[DD * DD];
__device__ __nv_bfloat16 g_WBT_h[1024 * DD],      g_WBT_l[1024 * DD];
__device__ __nv_bfloat16 g_WcoT_h[DD * 128],      g_WcoT_l[DD * 128];
__device__ __nv_bfloat16 g_mh[(size_t)NT * 128],  g_ml[(size_t)NT * 128];

// ---------------- helpers ----------------
__device__ __forceinline__ uint32_t smem_u32(const void* p) {
    uint32_t a;
    asm("{ .reg .u64 t; cvta.to.shared.u64 t, %1; cvt.u32.u64 %0, t; }" : "=r"(a) : "l"(p));
    return a;
}
__device__ __forceinline__ void bsplit(float v, __nv_bfloat16& h, __nv_bfloat16& l)
{
    h = __float2bfloat16(v);
    l = __float2bfloat16(v - __bfloat162float(h));
}
// ---- packed f32x2 ops (FFMA2 path, PTX-only) ----
__device__ __forceinline__ unsigned long long pk2(float x, float y) {
    unsigned long long r;
    asm("mov.b64 %0, {%1, %2};" : "=l"(r) : "f"(x), "f"(y));
    return r;
}
__device__ __forceinline__ void upk2(unsigned long long p, float& x, float& y) {
    asm("mov.b64 {%0, %1}, %2;" : "=f"(x), "=f"(y) : "l"(p));
}
__device__ __forceinline__ unsigned long long ffma2(unsigned long long a,
                                                    unsigned long long b,
                                                    unsigned long long c) {
    unsigned long long r;
    asm("fma.rn.f32x2 %0, %1, %2, %3;" : "=l"(r) : "l"(a), "l"(b), "l"(c));
    return r;
}
__device__ __forceinline__ unsigned long long fadd2(unsigned long long a,
                                                    unsigned long long b) {
    unsigned long long r;
    asm("add.rn.f32x2 %0, %1, %2;" : "=l"(r) : "l"(a), "l"(b));
    return r;
}

#define CPA16(dst, src)  asm volatile("cp.async.cg.shared.global [%0], [%1], 16;" :: "r"(dst), "l"(src))
#define CPA_COMMIT()     asm volatile("cp.async.commit_group;" ::: "memory")
#define CPA_WAIT0()      asm volatile("cp.async.wait_group 0;" ::: "memory")
#define CPA_WAIT1()      asm volatile("cp.async.wait_group 1;" ::: "memory")

#define MMA_BF16(d, a0, a1, a2, a3, b0, b1)                                   \
    asm volatile("mma.sync.aligned.m16n8k16.row.col.f32.bf16.bf16.f32 "       \
                 "{%0,%1,%2,%3}, {%4,%5,%6,%7}, {%8,%9}, {%0,%1,%2,%3};\n"    \
                 : "+f"(d[0]), "+f"(d[1]), "+f"(d[2]), "+f"(d[3])             \
                 : "r"(a0), "r"(a1), "r"(a2), "r"(a3), "r"(b0), "r"(b1))

// ---------------- x -> bf16 split ----------------
__global__ void xcvt_kernel(const float* __restrict__ x)
{
    int i = blockIdx.x * 256 + threadIdx.x;      // NT*DD = 2M
    __nv_bfloat16 h, l;
    bsplit(x[i], h, l);
    g_xh[i] = h; g_xl[i] = l;
}

// ---------------- transpose + split: src[K][N] fp32 -> dh/dl[N][K] bf16 ----
__global__ void tsplit_kernel(const float* __restrict__ src,
                              __nv_bfloat16* __restrict__ dh,
                              __nv_bfloat16* __restrict__ dl, int K, int N)
{
    __shared__ float t[32][33];
    int bn = blockIdx.x * 32, bk = blockIdx.y * 32;
    int tx = threadIdx.x, ty = threadIdx.y;
#pragma unroll
    for (int i = ty; i < 32; i += 8)
        t[i][tx] = src[(size_t)(bk + i) * N + bn + tx];
    __syncthreads();
#pragma unroll
    for (int i = ty; i < 32; i += 8) {
        __nv_bfloat16 h, l;
        bsplit(t[tx][i], h, l);                  // = src[bk+tx][bn+i]
        dh[(size_t)(bn + i) * K + bk + tx] = h;
        dl[(size_t)(bn + i) * K + bk + tx] = l;
    }
}

// ---------------- prep: fuse bridge+out weights (fp32) ----------------
__global__ void prep_kernel(const float* __restrict__ Wb, const float* __restrict__ bb,
                            const float* __restrict__ Wo, const float* __restrict__ bo)
{
    int idx = blockIdx.x * blockDim.x + threadIdx.x;   // 0..65535
    int pr = idx >> 9, j = idx & 511;
    float s = 0.f;
#pragma unroll
    for (int i = 0; i < 32; ++i)
        s = fmaf(Wb[pr * 32 + i], Wo[i * 512 + j], s);
    g_Wco[idx] = s;
    if (idx < 512) {
        float c = bo[idx];
#pragma unroll
        for (int i = 0; i < 32; ++i)
            c = fmaf(bb[i], Wo[i * 512 + idx], c);
        g_bco[idx] = c;
    }
}

// ---------------- reduce W_site over physical index -> W_B (fp32) ----------
__global__ __launch_bounds__(256) void wb_kernel(const float* __restrict__ Ws,
                                                 const float* __restrict__ bs)
{
    int idx = blockIdx.x * 256 + threadIdx.x;          // 0 .. 512*1024-1
    int d = idx >> 10, rem = idx & 1023;
    int l = rem >> 5, r = rem & 31;
    const float* p = Ws + (size_t)d * 4096 + l * 128 + r;   // coalesced in r
    g_WB[(size_t)d * 1024 + r * 32 + l] = p[0] + p[32] + p[64] + p[96];
    if (idx < 1024) {
        int ll = idx >> 5, rr = idx & 31;
        const float* q = bs + ll * 128 + rr;
        g_bB[rr * 32 + ll] = q[0] + q[32] + q[64] + q[96];
    }
}

// ============ bf16-split tensor GEMM: C = A[MxK] @ B[KxN] + bias ===========
#define HG_SMEM (2 * 40960)

__device__ __forceinline__ void hg_load(uint32_t sb,
    const __nv_bfloat16* __restrict__ Ah, const __nv_bfloat16* __restrict__ Al,
    const __nv_bfloat16* __restrict__ Bh, const __nv_bfloat16* __restrict__ Bl,
    int bm, int bn, int K, int k0, int tid)
{
#pragma unroll
    for (int q = 0; q < 2; ++q) {
        int id = tid + 256 * q;                  // 0..511
        int r = id >> 2, c = id & 3;
        uint32_t so = (uint32_t)(r * 80 + c * 16);
        size_t goA = (size_t)(bm + r) * K + k0 + c * 8;
        size_t goB = (size_t)(bn + r) * K + k0 + c * 8;
        CPA16(sb + so,          Ah + goA);
        CPA16(sb + 10240 + so,  Al + goA);
        CPA16(sb + 20480 + so,  Bh + goB);
        CPA16(sb + 30720 + so,  Bl + goB);
    }
}

__device__ __forceinline__ void hg_compute(const char* ss, float acc[4][4][4],
                                           int m0w, int n0w, int g, int tg)
{
    const char* sa_h = ss;
    const char* sa_l = ss + 10240;
    const char* sb_h = ss + 20480;
    const char* sb_l = ss + 30720;
#pragma unroll
    for (int kk = 0; kk < 2; ++kk) {
        int kb = kk * 32 + tg * 4;               // byte offset within row
        uint32_t ah[4][4], al[4][4];
#pragma unroll
        for (int mi = 0; mi < 4; ++mi) {
            int r0 = m0w + mi * 16 + g;
            ah[mi][0] = *(const uint32_t*)(sa_h + r0 * 80 + kb);
            ah[mi][1] = *(const uint32_t*)(sa_h + (r0 + 8) * 80 + kb);
            ah[mi][2] = *(const uint32_t*)(sa_h + r0 * 80 + kb + 16);
            ah[mi][3] = *(const uint32_t*)(sa_h + (r0 + 8) * 80 + kb + 16);
            al[mi][0] = *(const uint32_t*)(sa_l + r0 * 80 + kb);
            al[mi][1] = *(const uint32_t*)(sa_l + (r0 + 8) * 80 + kb);
            al[mi][2] = *(const uint32_t*)(sa_l + r0 * 80 + kb + 16);
            al[mi][3] = *(const uint32_t*)(sa_l + (r0 + 8) * 80 + kb + 16);
        }
#pragma unroll
        for (int ni = 0; ni < 4; ++ni) {
            int n0 = n0w + ni * 8 + g;
            uint32_t bh0 = *(const uint32_t*)(sb_h + n0 * 80 + kb);
            uint32_t bh1 = *(const uint32_t*)(sb_h + n0 * 80 + kb + 16);
            uint32_t bl0 = *(const uint32_t*)(sb_l + n0 * 80 + kb);
            uint32_t bl1 = *(const uint32_t*)(sb_l + n0 * 80 + kb + 16);
#pragma unroll
            for (int mi = 0; mi < 4; ++mi) {
                MMA_BF16(acc[mi][ni], ah[mi][0], ah[mi][1], ah[mi][2], ah[mi][3], bh0, bh1);
                MMA_BF16(acc[mi][ni], ah[mi][0], ah[mi][1], ah[mi][2], ah[mi][3], bl0, bl1);
                MMA_BF16(acc[mi][ni], al[mi][0], al[mi][1], al[mi][2], al[mi][3], bh0, bh1);
            }
        }
    }
}

__global__ __launch_bounds__(256, 1)
void hgemm2_kernel(const __nv_bfloat16* __restrict__ Ah, const __nv_bfloat16* __restrict__ Al,
                   const __nv_bfloat16* __restrict__ Bh, const __nv_bfloat16* __restrict__ Bl,
                   const float* __restrict__ bias, float* __restrict__ C,
                   int M, int N, int K)
{
    extern __shared__ __align__(16) char smem[];
    const int tid = threadIdx.x;
    const int warp = tid >> 5, lane = tid & 31;
    const int g = lane >> 2, tg = lane & 3;
    const int m0w = (warp >> 2) * 64;            // 0 | 64
    const int n0w = (warp & 3) * 32;             // 0..96
    const int bm = blockIdx.y * 128, bn = blockIdx.x * 128;
    const uint32_t sb = smem_u32(smem);

    float acc[4][4][4];
#pragma unroll
    for (int i = 0; i < 4; ++i)
#pragma unroll
        for (int j = 0; j < 4; ++j)
#pragma unroll
            for (int e = 0; e < 4; ++e) acc[i][j][e] = 0.f;

    const int nk = K >> 5;
    hg_load(sb, Ah, Al, Bh, Bl, bm, bn, K, 0, tid);
    CPA_COMMIT();
    for (int i = 0; i < nk; ++i) {
        if (i + 1 < nk) {
            hg_load(sb + ((i + 1) & 1) * 40960, Ah, Al, Bh, Bl, bm, bn, K, (i + 1) * 32, tid);
            CPA_COMMIT();
            CPA_WAIT1();
        } else {
            CPA_WAIT0();
        }
        __syncthreads();
        hg_compute(smem + (i & 1) * 40960, acc, m0w, n0w, g, tg);
        __syncthreads();
    }

#pragma unroll
    for (int mi = 0; mi < 4; ++mi) {
        int row = bm + m0w + mi * 16 + g;
#pragma unroll
        for (int ni = 0; ni < 4; ++ni) {
            int col = bn + n0w + ni * 8 + 2 * tg;
            float b0 = bias[col], b1 = bias[col + 1];
            *(float2*)&C[(size_t)row * N + col] =
                make_float2(acc[mi][ni][0] + b0, acc[mi][ni][1] + b1);
            *(float2*)&C[(size_t)(row + 8) * N + col] =
                make_float2(acc[mi][ni][2] + b0, acc[mi][ni][3] + b1);
        }
    }
}

// ---------------- c_t[r] = sum_l u_t[l] * B_t[l][r] (8 tokens/block) -------
__global__ __launch_bounds__(256) void c_kernel(const float* __restrict__ x)
{
    int t = blockIdx.x * 8 + (threadIdx.x >> 5);
    int r = threadIdx.x & 31;
    float u = x[(size_t)t * DD + r];           // lane l holds u_l
    const float* brow = g_Bmat + (size_t)t * 1024 + r * 32;
    float4 b4[8];
#pragma unroll
    for (int q = 0; q < 8; ++q) b4[q] = __ldg((const float4*)(brow + 4 * q));
    float c = 0.f;
#pragma unroll
    for (int q = 0; q < 8; ++q) {
        c = fmaf(__shfl_sync(0xffffffffu, u, 4 * q + 0), b4[q].x, c);
        c = fmaf(__shfl_sync(0xffffffffu, u, 4 * q + 1), b4[q].y, c);
        c = fmaf(__shfl_sync(0xffffffffu, u, 4 * q + 2), b4[q].z, c);
        c = fmaf(__shfl_sync(0xffffffffu, u, 4 * q + 3), b4[q].w, c);
    }
    g_c[(size_t)t * 32 + r] = c;
}

// ---------------- sequential scan: one warp per batch, packed f32x2 --------
// v_t = alpha_{t-1} * (v_{t-1} @ B_t) + c_t,  alpha = rsqrt(||v||^2 + 1e-24).
// Norm is accumulated from the SAME broadcast pairs the matvec uses (no
// butterfly); matvec + norm both run as packed FFMA2 (2 fp32 per instr).
__device__ __forceinline__ float scan_step(float v, const ulonglong2* Bv,
                                           float cc, float uu, float* leftp)
{
    const unsigned long long* b = (const unsigned long long*)Bv;  // 16 pairs
    unsigned long long pv[16];
#pragma unroll
    for (int i = 0; i < 16; ++i)
        pv[i] = pk2(__shfl_sync(0xffffffffu, v, 2 * i),
                    __shfl_sync(0xffffffffu, v, 2 * i + 1));

    unsigned long long w0 = 0, w1 = 0, w2 = 0, w3 = 0;
    unsigned long long s0 = 0, s1 = 0, s2 = 0, s3 = 0;
#pragma unroll
    for (int i = 0; i < 4; ++i) {
        w0 = ffma2(pv[i],      b[i],      w0);  s0 = ffma2(pv[i],      pv[i],      s0);
        w1 = ffma2(pv[i + 4],  b[i + 4],  w1);  s1 = ffma2(pv[i + 4],  pv[i + 4],  s1);
        w2 = ffma2(pv[i + 8],  b[i + 8],  w2);  s2 = ffma2(pv[i + 8],  pv[i + 8],  s2);
        w3 = ffma2(pv[i + 12], b[i + 12], w3);  s3 = ffma2(pv[i + 12], pv[i + 12], s3);
    }
    unsigned long long wp = fadd2(fadd2(w0, w1), fadd2(w2, w3));
    unsigned long long sp = fadd2(fadd2(s0, s1), fadd2(s2, s3));
    float wl, wh, sl, sh;
    upk2(wp, wl, wh);
    upk2(sp, sl, sh);
    float w = wl + wh;
    float s = sl + sh;

    float alpha = rsqrtf(s + 1e-24f);            // s==0 -> alpha*v == 0 == h0
    *leftp = fmaf(alpha, v, uu);
    return fmaf(alpha, w, cc);
}

__global__ void scan_kernel(const float* __restrict__ x)
{
    const int b = blockIdx.x;
    const int r = threadIdx.x;                 // 0..31
    const size_t tg0 = (size_t)b * LL;
    const float* Bbase = g_Bmat + tg0 * 1024 + r * 32;
    const float* cbase = g_c + tg0 * 32 + r;
    const float* ubase = x + tg0 * DD + r;
    float* lp = g_left + tg0 * 32 + r;

    ulonglong2 b0[4], b1[4], b2[4];
    float c0, c1, c2, u0, u1, u2;

#define PREF(PT, BUF, CC, UU) { \
        int tp_ = (PT); if (tp_ > (LL-1)) tp_ = LL-1; \
        const ulonglong2* bp_ = (const ulonglong2*)(Bbase + (size_t)tp_ * 1024); \
        BUF[0] = __ldg(bp_ + 0); BUF[1] = __ldg(bp_ + 1); \
        BUF[2] = __ldg(bp_ + 2); BUF[3] = __ldg(bp_ + 3); \
        CC = __ldg(cbase + (size_t)tp_ * 32); \
        UU = __ldg(ubase + (size_t)tp_ * DD); }

// each ulonglong2 = 16B; a 32-float row = 8 of them; use two 4-wide arrays
    ulonglong2 b0b[4], b1b[4], b2b[4];
#define PREF2(PT, BUF, BUFB, CC, UU) { \
        int tp_ = (PT); if (tp_ > (LL-1)) tp_ = LL-1; \
        const ulonglong2* bp_ = (const ulonglong2*)(Bbase + (size_t)tp_ * 1024); \
        BUF[0]  = __ldg(bp_ + 0); BUF[1]  = __ldg(bp_ + 1); \
        BUF[2]  = __ldg(bp_ + 2); BUF[3]  = __ldg(bp_ + 3); \
        BUFB[0] = __ldg(bp_ + 4); BUFB[1] = __ldg(bp_ + 5); \
        BUFB[2] = __ldg(bp_ + 6); BUFB[3] = __ldg(bp_ + 7); \
        CC = __ldg(cbase + (size_t)tp_ * 32); \
        UU = __ldg(ubase + (size_t)tp_ * DD); }

    ulonglong2 Bfull[8];
#define STEP(BUF, BUFB, CC, UU) ( \
        Bfull[0] = BUF[0],  Bfull[1] = BUF[1],  Bfull[2] = BUF[2],  Bfull[3] = BUF[3], \
        Bfull[4] = BUFB[0], Bfull[5] = BUFB[1], Bfull[6] = BUFB[2], Bfull[7] = BUFB[3], \
        scan_step(v, Bfull, CC, UU, lp))

    PREF2(0, b0, b0b, c0, u0);
    PREF2(1, b1, b1b, c1, u1);
    float v = 0.f;

#pragma unroll 1
    for (int t = 0; t < LL - 1; t += 3) {
        PREF2(t + 2, b2, b2b, c2, u2);
        v = STEP(b0, b0b, c0, u0); lp += 32;
        PREF2(t + 3, b0, b0b, c0, u0);
        v = STEP(b1, b1b, c1, u1); lp += 32;
        PREF2(t + 4, b1, b1b, c1, u1);
        v = STEP(b2, b2b, c2, u2); lp += 32;
    }
    // main loop covers t = 0..1022 (341 blocks of 3); tail t = 1023 in b0
    v = STEP(b0, b0b, c0, u0);
#undef PREF
#undef PREF2
#undef STEP
}

// ------- recover Mt per token; emit bf16 split for the final GEMM ----------
__global__ __launch_bounds__(128) void mrec_kernel()
{
    __shared__ float sleft[32];
    int t = blockIdx.x, tid = threadIdx.x;
    if (tid < 32) sleft[tid] = g_left[(size_t)t * 32 + tid];
    __syncthreads();
    const float* row = g_site + (size_t)t * CSC;
    float m = 0.f;
#pragma unroll
    for (int l = 0; l < 32; ++l)
        m = fmaf(sleft[l], __ldcs(row + l * 128 + tid), m);   // streaming, coalesced
    __nv_bfloat16 h, lo;
    bsplit(m, h, lo);
    g_mh[(size_t)t * 128 + tid] = h;
    g_ml[(size_t)t * 128 + tid] = lo;
}

// ---------------- LayerNorm + sigmoid-gated residual ----------------
__global__ __launch_bounds__(256) void post_kernel(const float* __restrict__ x,
                                                   const float* __restrict__ gamma,
                                                   const float* __restrict__ beta,
                                                   float* __restrict__ out)
{
    __shared__ float red[256];
    int t = blockIdx.x, tid = threadIdx.x;
    size_t base = (size_t)t * DD;
    int j0 = tid, j1 = tid + 256;
    float y0 = g_y[base + j0], y1 = g_y[base + j1];

    red[tid] = y0 + y1;
    __syncthreads();
    for (int st = 128; st > 0; st >>= 1) {
        if (tid < st) red[tid] += red[tid + st];
        __syncthreads();
    }
    float mu = red[0] * (1.f / 512.f);
    __syncthreads();

    float d0 = y0 - mu, d1 = y1 - mu;
    red[tid] = d0 * d0 + d1 * d1;
    __syncthreads();
    for (int st = 128; st > 0; st >>= 1) {
        if (tid < st) red[tid] += red[tid + st];
        __syncthreads();
    }
    float var = red[0] * (1.f / 512.f);
    float rstd = rsqrtf(var + 1e-6f);

    float yn0 = d0 * rstd * gamma[j0] + beta[j0];
    float yn1 = d1 * rstd * gamma[j1] + beta[j1];
    float gl0 = g_gate[base + j0], gl1 = g_gate[base + j1];
    float gt0 = 1.f / (1.f + expf(-gl0));
    float gt1 = 1.f / (1.f + expf(-gl1));
    float xv0 = x[base + j0], xv1 = x[base + j1];
    out[base + j0] = gt0 * yn0 + (1.f - gt0) * xv0;
    out[base + j1] = gt1 * yn1 + (1.f - gt1) * xv1;
}

// ---------------- launch ----------------
extern "C" void kernel_launch(void* const* d_in, const int* in_sizes, int n_in,
                              void* d_out, int out_size)
{
    (void)in_sizes; (void)n_in; (void)out_size;
    const float* x       = (const float*)d_in[0];
    const float* W_site  = (const float*)d_in[1];
    const float* b_site  = (const float*)d_in[2];
    const float* W_bridge= (const float*)d_in[3];
    const float* b_bridge= (const float*)d_in[4];
    const float* W_out   = (const float*)d_in[5];
    const float* b_out   = (const float*)d_in[6];
    const float* gamma   = (const float*)d_in[7];
    const float* beta    = (const float*)d_in[8];
    const float* W_gate  = (const float*)d_in[9];
    const float* b_gate  = (const float*)d_in[10];
    float* out = (float*)d_out;

    static float *p_site, *p_gate, *p_y, *p_WB, *p_bB, *p_Wco, *p_bco, *p_Bmat;
    static __nv_bfloat16 *p_xh, *p_xl, *p_WsTh, *p_WsTl, *p_WgTh, *p_WgTl,
                         *p_WBTh, *p_WBTl, *p_WcoTh, *p_WcoTl, *p_mh, *p_ml;
    static cudaStream_t s1;
    static cudaEvent_t ev0, evS, evG;
    static bool inited = false;
    if (!inited) {
        cudaGetSymbolAddress((void**)&p_site,  g_site);
        cudaGetSymbolAddress((void**)&p_gate,  g_gate);
        cudaGetSymbolAddress((void**)&p_y,     g_y);
        cudaGetSymbolAddress((void**)&p_WB,    g_WB);
        cudaGetSymbolAddress((void**)&p_bB,    g_bB);
        cudaGetSymbolAddress((void**)&p_Wco,   g_Wco);
        cudaGetSymbolAddress((void**)&p_bco,   g_bco);
        cudaGetSymbolAddress((void**)&p_Bmat,  g_Bmat);
        cudaGetSymbolAddress((void**)&p_xh,    g_xh);
        cudaGetSymbolAddress((void**)&p_xl,    g_xl);
        cudaGetSymbolAddress((void**)&p_WsTh,  g_WsT_h);
        cudaGetSymbolAddress((void**)&p_WsTl,  g_WsT_l);
        cudaGetSymbolAddress((void**)&p_WgTh,  g_WgT_h);
        cudaGetSymbolAddress((void**)&p_WgTl,  g_WgT_l);
        cudaGetSymbolAddress((void**)&p_WBTh,  g_WBT_h);
        cudaGetSymbolAddress((void**)&p_WBTl,  g_WBT_l);
        cudaGetSymbolAddress((void**)&p_WcoTh, g_WcoT_h);
        cudaGetSymbolAddress((void**)&p_WcoTl, g_WcoT_l);
        cudaGetSymbolAddress((void**)&p_mh,    g_mh);
        cudaGetSymbolAddress((void**)&p_ml,    g_ml);
        cudaStreamCreateWithFlags(&s1, cudaStreamNonBlocking);
        cudaEventCreateWithFlags(&ev0, cudaEventDisableTiming);
        cudaEventCreateWithFlags(&evS, cudaEventDisableTiming);
        cudaEventCreateWithFlags(&evG, cudaEventDisableTiming);
        cudaFuncSetAttribute(hgemm2_kernel, cudaFuncAttributeMaxDynamicSharedMemorySize, HG_SMEM);
        inited = true;
    }

    // shared prologue: x split (both branches need it)
    xcvt_kernel<<<(NT * DD) / 256, 256>>>(x);
    cudaEventRecord(ev0, 0);
    cudaStreamWaitEvent(s1, ev0, 0);

    // ---- side stream: prep + weight converts + site & gate GEMMs ----
    prep_kernel<<<256, 256, 0, s1>>>(W_bridge, b_bridge, W_out, b_out);
    tsplit_kernel<<<dim3(16, 4),  dim3(32, 8), 0, s1>>>(p_Wco,  p_WcoTh, p_WcoTl, 128, 512);
    tsplit_kernel<<<dim3(128,16), dim3(32, 8), 0, s1>>>(W_site, p_WsTh,  p_WsTl,  512, 4096);
    tsplit_kernel<<<dim3(16, 16), dim3(32, 8), 0, s1>>>(W_gate, p_WgTh,  p_WgTl,  512, 512);
    hgemm2_kernel<<<dim3(CSC/128, NT/128), 256, HG_SMEM, s1>>>(
        p_xh, p_xl, p_WsTh, p_WsTl, b_site, p_site, NT, CSC, DD);
    cudaEventRecord(evS, s1);
    hgemm2_kernel<<<dim3(DD/128, NT/128), 256, HG_SMEM, s1>>>(
        p_xh, p_xl, p_WgTh, p_WgTl, b_gate, p_gate, NT, DD, DD);
    cudaEventRecord(evG, s1);

    // ---- main stream: B-matrix path + scan ----
    wb_kernel<<<2048, 256>>>(W_site, b_site);
    tsplit_kernel<<<dim3(32, 16), dim3(32, 8)>>>(p_WB, p_WBTh, p_WBTl, 512, 1024);
    hgemm2_kernel<<<dim3(1024/128, NT/128), 256, HG_SMEM>>>(
        p_xh, p_xl, p_WBTh, p_WBTl, p_bB, p_Bmat, NT, 1024, DD);
    c_kernel<<<NT / 8, 256>>>(x);
    scan_kernel<<<BB, 32>>>(x);

    // join: site needed for M recovery, then final GEMM
    cudaStreamWaitEvent(0, evS, 0);
    mrec_kernel<<<NT, 128>>>();
    hgemm2_kernel<<<dim3(DD/128, NT/128), 256, HG_SMEM>>>(
        p_mh, p_ml, p_WcoTh, p_WcoTl, p_bco, p_y, NT, DD, 128);

    // join: gate needed for the epilogue
    cudaStreamWaitEvent(0, evG, 0);
    post_kernel<<<NT, 256>>>(x, gamma, beta, out);
}